// round 5
// baseline (speedup 1.0000x reference)
#include <cuda_runtime.h>

// AttentionStem: per-pixel 4x4 local window attention. B=4, IC=3, OC=64, H=W=128.
// R5 (= R4 resubmit after infra failure): two kernels — parallel prep (~1us,
// shfl-reduced emb dots, all-64-channel wv) + attn with copy-only prologue
// (single barrier), 64 regs / 8 CTAs per SM, packed f32x2 mainloop.

typedef unsigned long long u64;

#define LOG2E 1.4426950408889634f

__device__ __forceinline__ u64 pk2(float lo, float hi) {
    u64 r; asm("mov.b64 %0,{%1,%2};" : "=l"(r) : "f"(lo), "f"(hi)); return r;
}
__device__ __forceinline__ void upk2(u64 a, float& lo, float& hi) {
    asm("mov.b64 {%0,%1},%2;" : "=f"(lo), "=f"(hi) : "l"(a));
}
__device__ __forceinline__ u64 fma2_(u64 a, u64 b, u64 c) {
    u64 r; asm("fma.rn.f32x2 %0,%1,%2,%3;" : "=l"(r) : "l"(a), "l"(b), "l"(c)); return r;
}
__device__ __forceinline__ u64 mul2_(u64 a, u64 b) {
    u64 r; asm("mul.rn.f32x2 %0,%1,%2;" : "=l"(r) : "l"(a), "l"(b)); return r;
}
__device__ __forceinline__ u64 add2_(u64 a, u64 b) {
    u64 r; asm("add.rn.f32x2 %0,%1,%2;" : "=l"(r) : "l"(a), "l"(b)); return r;
}
__device__ __forceinline__ float ex2_(float x) {
    float r; asm("ex2.approx.f32 %0,%1;" : "=f"(r) : "f"(x)); return r;
}
__device__ __forceinline__ float lo32(u64 a) {
    return __int_as_float((int)(unsigned)a);
}

// Precomputed: mixed value weights (u64-packed pairs) and folded q/k weights.
__device__ u64    g_wv[64 * 24];   // [o][c][p], float view [o*48 + c*16 + ij]
__device__ float4 g_kw[64];
__device__ float4 g_qw[64];        // pre-scaled by LOG2E

__global__ void prep_kernel(const float* __restrict__ key_w,
                            const float* __restrict__ query_w,
                            const float* __restrict__ value_w,
                            const float* __restrict__ emb_a,
                            const float* __restrict__ emb_b,
                            const float* __restrict__ emb_mix) {
    __shared__ float sh_lab[32];   // la: [i*4+m], lb: [16 + j*4+m]
    __shared__ float sh_emb[4][16];
    int t = threadIdx.x;

    // Stage 1: la/lb dots, 4 lanes per output, shfl-reduced.
    {
        int outi = t >> 2;                 // 0..31: ab*16 + i4*4 + m
        int chunk = t & 3;
        int m = outi & 3, i4 = (outi >> 2) & 3, ab = outi >> 4;
        const float* e = ab ? emb_b : emb_a;
        float s = 0.f;
#pragma unroll
        for (int oo = 0; oo < 16; oo++) {
            int o = chunk * 16 + oo;
            s += emb_mix[m * 64 + o] * e[o * 4 + i4];
        }
        s += __shfl_xor_sync(0xffffffffu, s, 1);
        s += __shfl_xor_sync(0xffffffffu, s, 2);
        if (chunk == 0) sh_lab[outi] = s;
    }
    __syncthreads();

    // Stage 2: softmax over m per window position.
    if (t < 16) {
        int i = t >> 2, j = t & 3;
        float lg[4];
#pragma unroll
        for (int m = 0; m < 4; m++)
            lg[m] = sh_lab[(i << 2) + m] + sh_lab[16 + (j << 2) + m];
        float mx = fmaxf(fmaxf(lg[0], lg[1]), fmaxf(lg[2], lg[3]));
        float e[4], s = 0.f;
#pragma unroll
        for (int m = 0; m < 4; m++) { e[m] = __expf(lg[m] - mx); s += e[m]; }
        float inv = __fdividef(1.f, s);
#pragma unroll
        for (int m = 0; m < 4; m++) sh_emb[m][t] = e[m] * inv;
    }
    __syncthreads();

    // Stage 3: mixed value weights, all 64 channels (3072 floats, 24/thread).
    float* wvf = (float*)g_wv;
    for (int f = t; f < 3072; f += 128) {
        int o = f / 48, r = f % 48, c = r >> 4, ij = r & 15;
        float acc = 0.f;
#pragma unroll
        for (int m = 0; m < 4; m++)
            acc += sh_emb[m][ij] * value_w[(m * 64 + o) * 3 + c];
        wvf[f] = acc;
    }
    // Stage 3b: packed k/q weights.
    if (t < 64) {
        g_kw[t] = make_float4(key_w[t * 3], key_w[t * 3 + 1], key_w[t * 3 + 2], 0.f);
        g_qw[t] = make_float4(query_w[t * 3] * LOG2E,
                              query_w[t * 3 + 1] * LOG2E,
                              query_w[t * 3 + 2] * LOG2E, 0.f);
    }
}

__global__ __launch_bounds__(128, 8)
void attn_kernel(const float* __restrict__ x, float* __restrict__ out) {
    __shared__ float  sh_x[3][4][132];   // [c][window row][padded col]
    __shared__ float4 sh_kw[16];
    __shared__ float4 sh_qw[16];
    __shared__ u64    sh_wv[16 * 24];    // [o][c][p]

    int tid = threadIdx.x;
    int oq = blockIdx.x & 3;             // quarter of the 64 channels
    int bh = blockIdx.x >> 2;
    int b = bh >> 7;
    int h = bh & 127;

    // Copy-only prologue: x tile + wv slice + kw/qw slice; single barrier.
    for (int idx = tid; idx < 1584; idx += 128) {
        int c = idx / 528, rem = idx % 528, r = rem / 132, cc = rem % 132;
        int hr = h - 2 + r, wc = cc - 2;
        float v = 0.f;
        if (hr >= 0 && hr < 128 && wc >= 0 && wc < 128)
            v = x[((b * 3 + c) * 128 + hr) * 128 + wc];
        sh_x[c][r][cc] = v;
    }
    // wv slice: 384 u64 = 192 ulonglong2; threads 0..127 take one, 0..63 a second.
    {
        const ulonglong2* src = (const ulonglong2*)(g_wv + oq * 384);
        ulonglong2* dst = (ulonglong2*)sh_wv;
        dst[tid] = src[tid];
        if (tid < 64) dst[128 + tid] = src[128 + tid];
    }
    if (tid < 16) {
        sh_kw[tid] = g_kw[oq * 16 + tid];
        sh_qw[tid] = g_qw[oq * 16 + tid];
    }
    __syncthreads();

    // Window into registers, packed by (same i, adjacent j) pairs.
    int w = tid;
    u64 wp0[8], wp1[8], wp2[8];
#pragma unroll
    for (int p = 0; p < 8; p++) {
        int i = p >> 1, j0 = (p & 1) * 2;
        wp0[p] = pk2(sh_x[0][i][w + j0], sh_x[0][i][w + j0 + 1]);
        wp1[p] = pk2(sh_x[1][i][w + j0], sh_x[1][i][w + j0 + 1]);
        wp2[p] = pk2(sh_x[2][i][w + j0], sh_x[2][i][w + j0 + 1]);
    }

    float* outp = out + (((b * 64) + oq * 16) * 128 + h) * 128 + w;

#pragma unroll 2
    for (int o = 0; o < 16; o++) {
        float4 qw = sh_qw[o];
        // center pixel = low half of pair 5 (i=2, j=2)
        float q = qw.x * lo32(wp0[5]) + qw.y * lo32(wp1[5]) + qw.z * lo32(wp2[5]);
        float4 kw = sh_kw[o];
        float qk0 = q * kw.x, qk1 = q * kw.y, qk2 = q * kw.z;
        u64 k0 = pk2(qk0, qk0), k1 = pk2(qk1, qk1), k2 = pk2(qk2, qk2);
        const u64* wvp = sh_wv + o * 24;

        u64 acc = 0ull, ss = 0ull;
#pragma unroll
        for (int pp = 0; pp < 4; pp++) {
            ulonglong2 wv0 = *(const ulonglong2*)(wvp + 2 * pp);
            ulonglong2 wv1 = *(const ulonglong2*)(wvp + 8 + 2 * pp);
            ulonglong2 wv2 = *(const ulonglong2*)(wvp + 16 + 2 * pp);
            {
                int p = 2 * pp;
                u64 l2 = fma2_(k0, wp0[p], fma2_(k1, wp1[p], mul2_(k2, wp2[p])));
                float l0, l1; upk2(l2, l0, l1);
                u64 e2 = pk2(ex2_(l0), ex2_(l1));
                u64 v2 = fma2_(wv0.x, wp0[p], fma2_(wv1.x, wp1[p], mul2_(wv2.x, wp2[p])));
                acc = fma2_(e2, v2, acc);
                ss  = add2_(e2, ss);
            }
            {
                int p = 2 * pp + 1;
                u64 l2 = fma2_(k0, wp0[p], fma2_(k1, wp1[p], mul2_(k2, wp2[p])));
                float l0, l1; upk2(l2, l0, l1);
                u64 e2 = pk2(ex2_(l0), ex2_(l1));
                u64 v2 = fma2_(wv0.y, wp0[p], fma2_(wv1.y, wp1[p], mul2_(wv2.y, wp2[p])));
                acc = fma2_(e2, v2, acc);
                ss  = add2_(e2, ss);
            }
        }
        float a0, a1, s0, s1;
        upk2(acc, a0, a1);
        upk2(ss, s0, s1);
        outp[o * 16384] = __fdividef(a0 + a1, s0 + s1);
    }
}

extern "C" void kernel_launch(void* const* d_in, const int* in_sizes, int n_in,
                              void* d_out, int out_size) {
    const float* x       = (const float*)d_in[0];
    const float* key_w   = (const float*)d_in[1];
    const float* query_w = (const float*)d_in[2];
    const float* value_w = (const float*)d_in[3];
    const float* emb_a   = (const float*)d_in[4];
    const float* emb_b   = (const float*)d_in[5];
    const float* emb_mix = (const float*)d_in[6];
    float* out = (float*)d_out;

    prep_kernel<<<1, 128>>>(key_w, query_w, value_w, emb_a, emb_b, emb_mix);
    attn_kernel<<<2048, 128>>>(x, out);
}

// round 6
// speedup vs baseline: 1.1804x; 1.1804x over previous
#include <cuda_runtime.h>

// AttentionStem: per-pixel 4x4 local window attention. B=4, IC=3, OC=64, H=W=128.
// R6: revert 64-reg clamp (measured regression R3/R5); keep fast prep;
//     2 output rows per block (256 threads, grid 1024, 5-row shared tile).

typedef unsigned long long u64;

#define LOG2E 1.4426950408889634f

__device__ __forceinline__ u64 pk2(float lo, float hi) {
    u64 r; asm("mov.b64 %0,{%1,%2};" : "=l"(r) : "f"(lo), "f"(hi)); return r;
}
__device__ __forceinline__ void upk2(u64 a, float& lo, float& hi) {
    asm("mov.b64 {%0,%1},%2;" : "=f"(lo), "=f"(hi) : "l"(a));
}
__device__ __forceinline__ u64 fma2_(u64 a, u64 b, u64 c) {
    u64 r; asm("fma.rn.f32x2 %0,%1,%2,%3;" : "=l"(r) : "l"(a), "l"(b), "l"(c)); return r;
}
__device__ __forceinline__ u64 mul2_(u64 a, u64 b) {
    u64 r; asm("mul.rn.f32x2 %0,%1,%2;" : "=l"(r) : "l"(a), "l"(b)); return r;
}
__device__ __forceinline__ u64 add2_(u64 a, u64 b) {
    u64 r; asm("add.rn.f32x2 %0,%1,%2;" : "=l"(r) : "l"(a), "l"(b)); return r;
}
__device__ __forceinline__ float ex2_(float x) {
    float r; asm("ex2.approx.f32 %0,%1;" : "=f"(r) : "f"(x)); return r;
}
__device__ __forceinline__ float lo32(u64 a) {
    return __int_as_float((int)(unsigned)a);
}

// Precomputed: mixed value weights (u64-packed pairs) and folded q/k weights.
__device__ u64    g_wv[64 * 24];   // [o][c][p], float view [o*48 + c*16 + ij]
__device__ float4 g_kw[64];
__device__ float4 g_qw[64];        // pre-scaled by LOG2E

__global__ void prep_kernel(const float* __restrict__ key_w,
                            const float* __restrict__ query_w,
                            const float* __restrict__ value_w,
                            const float* __restrict__ emb_a,
                            const float* __restrict__ emb_b,
                            const float* __restrict__ emb_mix) {
    __shared__ float sh_lab[32];   // la: [i*4+m], lb: [16 + j*4+m]
    __shared__ float sh_emb[4][16];
    int t = threadIdx.x;

    // Stage 1: la/lb dots, 4 lanes per output, shfl-reduced.
    {
        int outi = t >> 2;                 // 0..31: ab*16 + i4*4 + m
        int chunk = t & 3;
        int m = outi & 3, i4 = (outi >> 2) & 3, ab = outi >> 4;
        const float* e = ab ? emb_b : emb_a;
        float s = 0.f;
#pragma unroll
        for (int oo = 0; oo < 16; oo++) {
            int o = chunk * 16 + oo;
            s += emb_mix[m * 64 + o] * e[o * 4 + i4];
        }
        s += __shfl_xor_sync(0xffffffffu, s, 1);
        s += __shfl_xor_sync(0xffffffffu, s, 2);
        if (chunk == 0) sh_lab[outi] = s;
    }
    __syncthreads();

    // Stage 2: softmax over m per window position.
    if (t < 16) {
        int i = t >> 2, j = t & 3;
        float lg[4];
#pragma unroll
        for (int m = 0; m < 4; m++)
            lg[m] = sh_lab[(i << 2) + m] + sh_lab[16 + (j << 2) + m];
        float mx = fmaxf(fmaxf(lg[0], lg[1]), fmaxf(lg[2], lg[3]));
        float e[4], s = 0.f;
#pragma unroll
        for (int m = 0; m < 4; m++) { e[m] = __expf(lg[m] - mx); s += e[m]; }
        float inv = __fdividef(1.f, s);
#pragma unroll
        for (int m = 0; m < 4; m++) sh_emb[m][t] = e[m] * inv;
    }
    __syncthreads();

    // Stage 3: mixed value weights, all 64 channels (3072 floats, 24/thread).
    float* wvf = (float*)g_wv;
    for (int f = t; f < 3072; f += 128) {
        int o = f / 48, r = f % 48, c = r >> 4, ij = r & 15;
        float acc = 0.f;
#pragma unroll
        for (int m = 0; m < 4; m++)
            acc += sh_emb[m][ij] * value_w[(m * 64 + o) * 3 + c];
        wvf[f] = acc;
    }
    // Stage 3b: packed k/q weights.
    if (t < 64) {
        g_kw[t] = make_float4(key_w[t * 3], key_w[t * 3 + 1], key_w[t * 3 + 2], 0.f);
        g_qw[t] = make_float4(query_w[t * 3] * LOG2E,
                              query_w[t * 3 + 1] * LOG2E,
                              query_w[t * 3 + 2] * LOG2E, 0.f);
    }
}

__global__ __launch_bounds__(256)
void attn_kernel(const float* __restrict__ x, float* __restrict__ out) {
    __shared__ float  sh_x[3][5][132];   // [c][tile row][padded col]
    __shared__ float4 sh_kw[16];
    __shared__ float4 sh_qw[16];
    __shared__ u64    sh_wv[16 * 24];    // [o][c][p]

    int tid = threadIdx.x;
    int oq = blockIdx.x & 3;             // quarter of the 64 channels
    int rest = blockIdx.x >> 2;
    int b = rest >> 6;
    int hp = rest & 63;                  // row pair index
    int h0 = hp * 2;

    // Copy-only prologue: 5-row x tile + wv slice + kw/qw slice; single barrier.
    for (int idx = tid; idx < 3 * 5 * 132; idx += 256) {
        int c = idx / 660, rem = idx % 660, r = rem / 132, cc = rem % 132;
        int hr = h0 - 2 + r, wc = cc - 2;
        float v = 0.f;
        if (hr >= 0 && hr < 128 && wc >= 0 && wc < 128)
            v = x[((b * 3 + c) * 128 + hr) * 128 + wc];
        sh_x[c][r][cc] = v;
    }
    // wv slice: 384 u64 = 192 ulonglong2 over 256 threads.
    if (tid < 192) {
        const ulonglong2* src = (const ulonglong2*)(g_wv + oq * 384);
        ((ulonglong2*)sh_wv)[tid] = src[tid];
    }
    if (tid >= 192 && tid < 208) {
        sh_kw[tid - 192] = g_kw[oq * 16 + (tid - 192)];
        sh_qw[tid - 192] = g_qw[oq * 16 + (tid - 192)];
    }
    __syncthreads();

    // This thread's pixel: row group r0 (0/1), column w.
    int r0 = tid >> 7;
    int w = tid & 127;

    // Window into registers, packed by (same i, adjacent j) pairs.
    u64 wp0[8], wp1[8], wp2[8];
#pragma unroll
    for (int p = 0; p < 8; p++) {
        int i = (p >> 1) + r0, j0 = (p & 1) * 2;
        wp0[p] = pk2(sh_x[0][i][w + j0], sh_x[0][i][w + j0 + 1]);
        wp1[p] = pk2(sh_x[1][i][w + j0], sh_x[1][i][w + j0 + 1]);
        wp2[p] = pk2(sh_x[2][i][w + j0], sh_x[2][i][w + j0 + 1]);
    }

    float* outp = out + (((b * 64) + oq * 16) * 128 + (h0 + r0)) * 128 + w;

#pragma unroll 2
    for (int o = 0; o < 16; o++) {
        float4 qw = sh_qw[o];
        // center pixel = low half of pair 5 (i=2, j=2)
        float q = qw.x * lo32(wp0[5]) + qw.y * lo32(wp1[5]) + qw.z * lo32(wp2[5]);
        float4 kw = sh_kw[o];
        float qk0 = q * kw.x, qk1 = q * kw.y, qk2 = q * kw.z;
        u64 k0 = pk2(qk0, qk0), k1 = pk2(qk1, qk1), k2 = pk2(qk2, qk2);
        const u64* wvp = sh_wv + o * 24;

        u64 acc = 0ull, ss = 0ull;
#pragma unroll
        for (int pp = 0; pp < 4; pp++) {
            ulonglong2 wv0 = *(const ulonglong2*)(wvp + 2 * pp);
            ulonglong2 wv1 = *(const ulonglong2*)(wvp + 8 + 2 * pp);
            ulonglong2 wv2 = *(const ulonglong2*)(wvp + 16 + 2 * pp);
            {
                int p = 2 * pp;
                u64 l2 = fma2_(k0, wp0[p], fma2_(k1, wp1[p], mul2_(k2, wp2[p])));
                float l0, l1; upk2(l2, l0, l1);
                u64 e2 = pk2(ex2_(l0), ex2_(l1));
                u64 v2 = fma2_(wv0.x, wp0[p], fma2_(wv1.x, wp1[p], mul2_(wv2.x, wp2[p])));
                acc = fma2_(e2, v2, acc);
                ss  = add2_(e2, ss);
            }
            {
                int p = 2 * pp + 1;
                u64 l2 = fma2_(k0, wp0[p], fma2_(k1, wp1[p], mul2_(k2, wp2[p])));
                float l0, l1; upk2(l2, l0, l1);
                u64 e2 = pk2(ex2_(l0), ex2_(l1));
                u64 v2 = fma2_(wv0.y, wp0[p], fma2_(wv1.y, wp1[p], mul2_(wv2.y, wp2[p])));
                acc = fma2_(e2, v2, acc);
                ss  = add2_(e2, ss);
            }
        }
        float a0, a1, s0, s1;
        upk2(acc, a0, a1);
        upk2(ss, s0, s1);
        outp[o * 16384] = __fdividef(a0 + a1, s0 + s1);
    }
}

extern "C" void kernel_launch(void* const* d_in, const int* in_sizes, int n_in,
                              void* d_out, int out_size) {
    const float* x       = (const float*)d_in[0];
    const float* key_w   = (const float*)d_in[1];
    const float* query_w = (const float*)d_in[2];
    const float* value_w = (const float*)d_in[3];
    const float* emb_a   = (const float*)d_in[4];
    const float* emb_b   = (const float*)d_in[5];
    const float* emb_mix = (const float*)d_in[6];
    float* out = (float*)d_out;

    prep_kernel<<<1, 128>>>(key_w, query_w, value_w, emb_a, emb_b, emb_mix);
    attn_kernel<<<1024, 256>>>(x, out);
}